// round 13
// baseline (speedup 1.0000x reference)
#include <cuda_runtime.h>

#define W_IMG 256
#define H_IMG 256
#define TILE 16
#define NG 8192
#define NSEG 8
#define SEG (NG / NSEG)           // 1024 gaussians per segment
#define CPS 8                     // chunks per segment (1 per warp)
#define CHUNKSZ (SEG / CPS)       // 128
#define NTILE 256
#define MIN_W 1e-6f
#define LOG2E 1.4426950408889634f
#define NPIX (W_IMG * H_IMG)

typedef unsigned long long u64;
typedef unsigned short u16;

__device__ float4 g_scratch[NSEG][NPIX];   // (cr,cg,cb,T)
__device__ int    g_done[NTILE];           // zero-init; winner resets each run

__device__ __forceinline__ float ex2_fast(float x) {
    float y; asm("ex2.approx.f32 %0, %1;" : "=f"(y) : "f"(x)); return y;
}
__device__ __forceinline__ float lg2_fast(float x) {
    float y; asm("lg2.approx.f32 %0, %1;" : "=f"(y) : "f"(x)); return y;
}
__device__ __forceinline__ u64 pack2(float lo, float hi) {
    u64 r; asm("mov.b64 %0, {%1, %2};" : "=l"(r) : "f"(lo), "f"(hi)); return r;
}
__device__ __forceinline__ void unpack2(u64 v, float& lo, float& hi) {
    asm("mov.b64 {%0, %1}, %2;" : "=f"(lo), "=f"(hi) : "l"(v));
}
__device__ __forceinline__ u64 f2add(u64 a, u64 b) {
    u64 d; asm("add.rn.f32x2 %0, %1, %2;" : "=l"(d) : "l"(a), "l"(b)); return d;
}
__device__ __forceinline__ u64 f2mul(u64 a, u64 b) {
    u64 d; asm("mul.rn.f32x2 %0, %1, %2;" : "=l"(d) : "l"(a), "l"(b)); return d;
}
__device__ __forceinline__ u64 f2fma(u64 a, u64 b, u64 c) {
    u64 d; asm("fma.rn.f32x2 %0, %1, %2, %3;" : "=l"(d) : "l"(a), "l"(b), "l"(c)); return d;
}
__device__ __forceinline__ float4 ldcg4(const float4* p) {
    float4 v;
    asm volatile("ld.global.cg.v4.f32 {%0,%1,%2,%3}, [%4];"
                 : "=f"(v.x), "=f"(v.y), "=f"(v.z), "=f"(v.w) : "l"(p));
    return v;
}

// ------------- fused: cull (per-warp, smem lists) + staged f32x2 composite + combine -------------
__global__ __launch_bounds__(256)
void gs_raster_kernel(const float* __restrict__ pxy,
                      const float* __restrict__ icov,
                      const float* __restrict__ radius,
                      const float* __restrict__ colors,
                      const float* __restrict__ opacity,
                      float* __restrict__ out)
{
    __shared__ u16        s_idx[SEG];   // survivor ids, depth order within each chunk
    __shared__ int        s_cnt[CPS];
    // pair-interleaved composite staging: slot j holds gaussians (2j, 2j+1)
    __shared__ ulonglong2 s_m [128];    // (-mx pair), (-my pair)
    __shared__ ulonglong2 s_ab[128];    // (a2 pair), (b2 pair)
    __shared__ ulonglong2 s_cd[128];    // (c2 pair), (d pair)
    __shared__ ulonglong2 s_rg[128];    // (r,g even), (r,g odd)
    __shared__ float2     s_b [128];    // (cb even, cb odd)
    __shared__ int        s_ret;

    const int tid  = threadIdx.x;
    const int lane = tid & 31;
    const int warp = tid >> 5;
    const int tile = blockIdx.x;
    const int seg  = blockIdx.y;
    const int tx   = tile & 15, ty = tile >> 4;

    // ---- cull phase: warp w culls chunk w of this block's segment ----
    {
        const float tx0 = (float)(tx * TILE), tx1 = tx0 + (float)TILE;
        const float ty0 = (float)(ty * TILE), ty1 = ty0 + (float)TILE;
        const int beg = seg * SEG + warp * CHUNKSZ;
        int cnt = 0;
        #pragma unroll
        for (int it = 0; it < CHUNKSZ / 32; ++it) {          // 4 iterations
            const int g = beg + it * 32 + lane;
            const float2 mp = ((const float2*)pxy)[g];
            const float  r  = radius[g];
            const bool keep = (floorf(mp.x - r) <= tx1) && (ceilf(mp.x + r) >= tx0)
                           && (floorf(mp.y - r) <= ty1) && (ceilf(mp.y + r) >= ty0);
            const unsigned m = __ballot_sync(0xffffffffu, keep);
            if (keep) {
                const int idx = cnt + __popc(m & ((1u << lane) - 1u));  // order-preserving
                s_idx[warp * CHUNKSZ + idx] = (u16)g;
            }
            cnt += __popc(m);
        }
        if (lane == 0) s_cnt[warp] = cnt;
    }
    __syncthreads();

    int total = 0;
    #pragma unroll
    for (int c = 0; c < CPS; ++c) total += s_cnt[c];

    const float fx = (float)(tx * TILE + (tid >> 4));
    const float fy = (float)(ty * TILE + (tid & 15));
    const u64 fxp = pack2(fx, fx);
    const u64 fyp = pack2(fy, fy);

    float T = 1.0f;
    u64   crg = pack2(0.0f, 0.0f);
    float cb  = 0.0f;

    for (int base = 0; base < total; base += 256) {
        if (base > 0 && __syncthreads_count(T >= MIN_W) == 0) break;

        const int s = base + tid;
        if (s < total) {
            int rem = s, c = 0;                   // locate sub-list (8 per-warp chunks)
            #pragma unroll
            for (int k = 0; k < CPS - 1; ++k)
                if (rem >= s_cnt[c]) { rem -= s_cnt[c]; ++c; }
            const int gi = (int)s_idx[c * CHUNKSZ + rem];

            // fold constants inline (once per staged survivor)
            const float2 mp = ((const float2*)pxy)[gi];
            const float4 ic = ((const float4*)icov)[gi];
            const float a2 = -0.5f * LOG2E * ic.x;
            const float b2 = -LOG2E * ic.y;
            const float c2 = -0.5f * LOG2E * ic.w;
            const float d  = -lg2_fast(1.0f + ex2_fast(-LOG2E * opacity[gi])); // log2(sigmoid)

            const int j = tid >> 1, e = tid & 1;
            float* pm  = (float*)&s_m[j];  pm[e]  = -mp.x; pm[2+e]  = -mp.y;
            float* pab = (float*)&s_ab[j]; pab[e] = a2;    pab[2+e] = b2;
            float* pcd = (float*)&s_cd[j]; pcd[e] = c2;    pcd[2+e] = d;
            float* prg = (float*)&s_rg[j]; prg[2*e] = colors[3*gi+0]; prg[2*e+1] = colors[3*gi+1];
            ((float*)&s_b[j])[e] = colors[3*gi+2];
        }
        const int m   = min(256, total - base);
        const int pm8 = (m + 7) & ~7;
        if (tid >= m && tid < pm8) {              // alpha == 0 sentinels
            const int j = tid >> 1, e = tid & 1;
            float* pm  = (float*)&s_m[j];  pm[e]  = 0.0f; pm[2+e]  = 0.0f;
            float* pab = (float*)&s_ab[j]; pab[e] = 0.0f; pab[2+e] = 0.0f;
            float* pcd = (float*)&s_cd[j]; pcd[e] = 0.0f; pcd[2+e] = -1e30f;
            float* prg = (float*)&s_rg[j]; prg[2*e] = 0.0f; prg[2*e+1] = 0.0f;
            ((float*)&s_b[j])[e] = 0.0f;
        }
        __syncthreads();

        if (T >= MIN_W) {
            const int npair = pm8 >> 1;
            for (int j = 0; j < npair; j += 4) {  // 4 pairs = 8 gaussians
                float al[8];
                #pragma unroll
                for (int p = 0; p < 4; ++p) {     // packed alpha evals
                    const ulonglong2 mm = s_m [j + p];
                    const ulonglong2 ab = s_ab[j + p];
                    const ulonglong2 cd = s_cd[j + p];
                    const u64 dx = f2add(fxp, mm.x);
                    const u64 dy = f2add(fyp, mm.y);
                    const u64 t1 = f2fma(ab.x, dx, f2mul(ab.y, dy));   // a2*dx + b2*dy
                    const u64 t2 = f2fma(f2mul(cd.x, dy), dy, cd.y);   // c2*dy^2 + d
                    const u64 q  = f2fma(t1, dx, t2);
                    float q0, q1; unpack2(q, q0, q1);
                    al[2*p]   = ex2_fast(q0);
                    al[2*p+1] = ex2_fast(q1);
                }
                #pragma unroll
                for (int p = 0; p < 4; ++p) {     // short serial T-chain
                    const ulonglong2 rg = s_rg[j + p];
                    const float2     bv = s_b [j + p];
                    {
                        const float a  = al[2*p];
                        const float Tn = fmaf(-a, T, T);
                        const float w  = (Tn >= MIN_W) ? T * a : 0.0f;
                        crg = f2fma(pack2(w, w), rg.x, crg);
                        cb  = fmaf(w, bv.x, cb);
                        T = Tn;
                    }
                    {
                        const float a  = al[2*p+1];
                        const float Tn = fmaf(-a, T, T);
                        const float w  = (Tn >= MIN_W) ? T * a : 0.0f;
                        crg = f2fma(pack2(w, w), rg.y, crg);
                        cb  = fmaf(w, bv.y, cb);
                        T = Tn;
                    }
                }
                if (T < MIN_W) break;             // monotone
            }
        }
    }

    float cr, cg; unpack2(crg, cr, cg);
    const int px = tx * TILE + (tid >> 4);
    const int py = ty * TILE + (tid & 15);
    const int pix = px * H_IMG + py;
    g_scratch[seg][pix] = make_float4(cr, cg, cb, T);

    // ---- fused combine: last block per tile composites the 8 segments ----
    __threadfence();
    __syncthreads();
    if (tid == 0) s_ret = atomicAdd(&g_done[tile], 1);
    __syncthreads();
    if (s_ret == NSEG - 1) {
        // back-to-front: color_k = c_k + T_k * color_{k+1}
        float rr = 0.0f, gg = 0.0f, bb = 0.0f;
        #pragma unroll
        for (int k = NSEG - 1; k >= 0; --k) {
            const float4 v = ldcg4(&g_scratch[k][pix]);
            rr = fmaf(v.w, rr, v.x);
            gg = fmaf(v.w, gg, v.y);
            bb = fmaf(v.w, bb, v.z);
        }
        out[3*pix + 0] = rr;
        out[3*pix + 1] = gg;
        out[3*pix + 2] = bb;
        if (tid == 0) g_done[tile] = 0;           // reset for next graph replay
    }
}

extern "C" void kernel_launch(void* const* d_in, const int* in_sizes, int n_in,
                              void* d_out, int out_size) {
    const float* pxy     = (const float*)d_in[0];
    const float* icov    = (const float*)d_in[1];
    const float* radius  = (const float*)d_in[2];
    const float* colors  = (const float*)d_in[3];
    const float* opacity = (const float*)d_in[4];
    float* out = (float*)d_out;

    dim3 rgrid(NTILE, NSEG);
    gs_raster_kernel<<<rgrid, 256>>>(pxy, icov, radius, colors, opacity, out);
}

// round 14
// speedup vs baseline: 1.1671x; 1.1671x over previous
#include <cuda_runtime.h>

#define W_IMG 256
#define H_IMG 256
#define TILE 16
#define NG 8192
#define NSEG 4
#define SEG (NG / NSEG)           // 2048 gaussians per segment
#define NWARP 4                   // warps per block (128 threads)
#define CHUNKSZ (SEG / NWARP)     // 512 gaussians culled per warp
#define NTILE 256
#define STAGE 128                 // staged gaussians per round (== threads)
#define MIN_W 1e-6f
#define LOG2E 1.4426950408889634f
#define NPIX (W_IMG * H_IMG)

typedef unsigned long long u64;
typedef unsigned short u16;

__device__ float4 g_scratch[NSEG][NPIX];   // (cr,cg,cb,T)
__device__ int    g_done[NTILE];           // zero-init; winner resets each run

__device__ __forceinline__ float ex2_fast(float x) {
    float y; asm("ex2.approx.f32 %0, %1;" : "=f"(y) : "f"(x)); return y;
}
__device__ __forceinline__ float lg2_fast(float x) {
    float y; asm("lg2.approx.f32 %0, %1;" : "=f"(y) : "f"(x)); return y;
}
__device__ __forceinline__ u64 pack2(float lo, float hi) {
    u64 r; asm("mov.b64 %0, {%1, %2};" : "=l"(r) : "f"(lo), "f"(hi)); return r;
}
__device__ __forceinline__ void unpack2(u64 v, float& lo, float& hi) {
    asm("mov.b64 {%0, %1}, %2;" : "=f"(lo), "=f"(hi) : "l"(v));
}
__device__ __forceinline__ u64 f2add(u64 a, u64 b) {
    u64 d; asm("add.rn.f32x2 %0, %1, %2;" : "=l"(d) : "l"(a), "l"(b)); return d;
}
__device__ __forceinline__ u64 f2sub(u64 a, u64 b) {
    u64 d; asm("sub.rn.f32x2 %0, %1, %2;" : "=l"(d) : "l"(a), "l"(b)); return d;
}
__device__ __forceinline__ u64 f2mul(u64 a, u64 b) {
    u64 d; asm("mul.rn.f32x2 %0, %1, %2;" : "=l"(d) : "l"(a), "l"(b)); return d;
}
__device__ __forceinline__ u64 f2fma(u64 a, u64 b, u64 c) {
    u64 d; asm("fma.rn.f32x2 %0, %1, %2, %3;" : "=l"(d) : "l"(a), "l"(b), "l"(c)); return d;
}
__device__ __forceinline__ float4 ldcg4(const float4* p) {
    float4 v;
    asm volatile("ld.global.cg.v4.f32 {%0,%1,%2,%3}, [%4];"
                 : "=f"(v.x), "=f"(v.y), "=f"(v.z), "=f"(v.w) : "l"(p));
    return v;
}

// ---- fused: per-warp cull -> smem lists; 2-pixel f32x2 composite; fused combine ----
__global__ __launch_bounds__(128)
void gs_raster_kernel(const float* __restrict__ pxy,
                      const float* __restrict__ icov,
                      const float* __restrict__ radius,
                      const float* __restrict__ colors,
                      const float* __restrict__ opacity,
                      float* __restrict__ out)
{
    __shared__ u16        s_idx[SEG];    // survivor ids, depth order within each chunk
    __shared__ int        s_cnt[NWARP];
    __shared__ float4     s_A[STAGE];    // -mx, a2, b2, d
    __shared__ ulonglong2 s_B[STAGE];    // (-my,-my), (c2,c2)
    __shared__ ulonglong2 s_C[STAGE];    // (r,r), (g,g)
    __shared__ u64        s_D[STAGE];    // (b,b)
    __shared__ int        s_ret;

    const int tid  = threadIdx.x;        // 0..127
    const int lane = tid & 31;
    const int warp = tid >> 5;
    const int tile = blockIdx.x;
    const int seg  = blockIdx.y;
    const int tx   = tile & 15, ty = tile >> 4;

    // ---- cull phase: warp w culls chunk w of this block's segment ----
    {
        const float tx0 = (float)(tx * TILE), tx1 = tx0 + (float)TILE;
        const float ty0 = (float)(ty * TILE), ty1 = ty0 + (float)TILE;
        const int beg = seg * SEG + warp * CHUNKSZ;
        int cnt = 0;
        #pragma unroll 4
        for (int it = 0; it < CHUNKSZ / 32; ++it) {          // 16 iterations
            const int g = beg + it * 32 + lane;
            const float2 mp = ((const float2*)pxy)[g];
            const float  r  = radius[g];
            const bool keep = (floorf(mp.x - r) <= tx1) && (ceilf(mp.x + r) >= tx0)
                           && (floorf(mp.y - r) <= ty1) && (ceilf(mp.y + r) >= ty0);
            const unsigned m = __ballot_sync(0xffffffffu, keep);
            if (keep) {
                const int idx = cnt + __popc(m & ((1u << lane) - 1u));  // order-preserving
                s_idx[warp * CHUNKSZ + idx] = (u16)g;
            }
            cnt += __popc(m);
        }
        if (lane == 0) s_cnt[warp] = cnt;
    }
    __syncthreads();

    int total = 0;
    #pragma unroll
    for (int c = 0; c < NWARP; ++c) total += s_cnt[c];

    // two pixels per thread: (x, y0) and (x, y0+8), same x
    const int xo = tid >> 3;             // 0..15
    const int yo = tid & 7;              // 0..7
    const float fx  = (float)(tx * TILE + xo);
    const u64   fyp = pack2((float)(ty * TILE + yo), (float)(ty * TILE + yo + 8));

    u64 T   = pack2(1.0f, 1.0f);
    u64 crr = 0, cgg = 0, cbb = 0;
    float tmax = 1.0f;

    for (int base = 0; base < total; base += STAGE) {
        if (base > 0 && __syncthreads_count(tmax >= MIN_W) == 0) break;

        const int s = base + tid;
        if (s < total) {
            int rem = s, c = 0;          // locate per-warp sub-list
            #pragma unroll
            for (int k = 0; k < NWARP - 1; ++k)
                if (rem >= s_cnt[c]) { rem -= s_cnt[c]; ++c; }
            const int gi = (int)s_idx[c * CHUNKSZ + rem];

            const float2 mp = ((const float2*)pxy)[gi];
            const float4 ic = ((const float4*)icov)[gi];
            const float a2 = -0.5f * LOG2E * ic.x;
            const float b2 = -LOG2E * ic.y;
            const float c2 = -0.5f * LOG2E * ic.w;
            const float d  = -lg2_fast(1.0f + ex2_fast(-LOG2E * opacity[gi])); // log2(sigmoid)
            const float cr0 = colors[3*gi+0], cg0 = colors[3*gi+1], cb0 = colors[3*gi+2];

            s_A[tid] = make_float4(-mp.x, a2, b2, d);
            s_B[tid] = make_ulonglong2(pack2(-mp.y, -mp.y), pack2(c2, c2));
            s_C[tid] = make_ulonglong2(pack2(cr0, cr0), pack2(cg0, cg0));
            s_D[tid] = pack2(cb0, cb0);
        }
        const int m   = min(STAGE, total - base);
        const int pm4 = (m + 3) & ~3;
        if (tid >= m && tid < pm4) {     // alpha == 0 sentinels (q = -1e30)
            s_A[tid] = make_float4(0.0f, 0.0f, 0.0f, -1e30f);
            s_B[tid] = make_ulonglong2(0ull, 0ull);
            s_C[tid] = make_ulonglong2(0ull, 0ull);
            s_D[tid] = 0ull;
        }
        __syncthreads();

        if (tmax >= MIN_W) {
            for (int j = 0; j < pm4; j += 4) {   // 4 gaussians x 2 pixels = 8 indep evals
                u64 qp[4];
                #pragma unroll
                for (int p = 0; p < 4; ++p) {
                    const float4 A = s_A[j + p];
                    const ulonglong2 B = s_B[j + p];
                    const float dx = fx + A.x;
                    const float u  = A.y * dx;
                    const float qs = fmaf(u, dx, A.w);       // a2*dx^2 + d
                    const float v  = A.z * dx;               // b2*dx
                    const u64 dyp = f2add(fyp, B.x);
                    const u64 w1  = f2fma(B.y, dyp, pack2(v, v));   // c2*dy + b2*dx
                    qp[p] = f2fma(w1, dyp, pack2(qs, qs));
                }
                #pragma unroll
                for (int p = 0; p < 4; ++p) {
                    float q0, q1; unpack2(qp[p], q0, q1);
                    const u64 alp = pack2(ex2_fast(q0), ex2_fast(q1)); // alpha per pixel
                    const ulonglong2 C = s_C[j + p];
                    const u64 wp = f2mul(T, alp);            // T*alpha
                    T = f2sub(T, wp);                         // T *= (1-alpha)
                    crr = f2fma(wp, C.x, crr);
                    cgg = f2fma(wp, C.y, cgg);
                    cbb = f2fma(wp, s_D[j + p], cbb);
                }
                float t0, t1; unpack2(T, t0, t1);
                tmax = fmaxf(t0, t1);
                if (tmax < MIN_W) break;         // monotone
            }
        }
    }

    // write per-segment scratch for both pixels
    float t0, t1;  unpack2(T,   t0, t1);
    float r0, r1;  unpack2(crr, r0, r1);
    float g0, g1;  unpack2(cgg, g0, g1);
    float b0, b1;  unpack2(cbb, b0, b1);
    const int px   = tx * TILE + xo;
    const int py0  = ty * TILE + yo;
    const int pix0 = px * H_IMG + py0;
    const int pix1 = pix0 + 8;
    g_scratch[seg][pix0] = make_float4(r0, g0, b0, t0);
    g_scratch[seg][pix1] = make_float4(r1, g1, b1, t1);

    // ---- fused combine: last block per tile composites the 4 segments ----
    __threadfence();
    __syncthreads();
    if (tid == 0) s_ret = atomicAdd(&g_done[tile], 1);
    __syncthreads();
    if (s_ret == NSEG - 1) {
        #pragma unroll
        for (int h = 0; h < 2; ++h) {
            const int pix = (h == 0) ? pix0 : pix1;
            float rr = 0.0f, gg = 0.0f, bb = 0.0f;   // back-to-front
            #pragma unroll
            for (int k = NSEG - 1; k >= 0; --k) {
                const float4 v = ldcg4(&g_scratch[k][pix]);
                rr = fmaf(v.w, rr, v.x);
                gg = fmaf(v.w, gg, v.y);
                bb = fmaf(v.w, bb, v.z);
            }
            out[3*pix + 0] = rr;
            out[3*pix + 1] = gg;
            out[3*pix + 2] = bb;
        }
        if (tid == 0) g_done[tile] = 0;              // reset for next graph replay
    }
}

extern "C" void kernel_launch(void* const* d_in, const int* in_sizes, int n_in,
                              void* d_out, int out_size) {
    const float* pxy     = (const float*)d_in[0];
    const float* icov    = (const float*)d_in[1];
    const float* radius  = (const float*)d_in[2];
    const float* colors  = (const float*)d_in[3];
    const float* opacity = (const float*)d_in[4];
    float* out = (float*)d_out;

    dim3 rgrid(NTILE, NSEG);
    gs_raster_kernel<<<rgrid, 128>>>(pxy, icov, radius, colors, opacity, out);
}

// round 15
// speedup vs baseline: 1.2428x; 1.0649x over previous
#include <cuda_runtime.h>

#define W_IMG 256
#define H_IMG 256
#define TILE 16
#define NG 8192
#define NSEG 8
#define SEG (NG / NSEG)           // 1024 gaussians per segment
#define NWARP 4                   // warps per block (128 threads)
#define CHUNKSZ (SEG / NWARP)     // 256 gaussians culled per warp
#define NTILE 256
#define STAGE 128                 // staged gaussians per round (== threads)
#define MIN_W 1e-6f
#define LOG2E 1.4426950408889634f
#define NPIX (W_IMG * H_IMG)

typedef unsigned long long u64;
typedef unsigned short u16;

__device__ float4 g_scratch[NSEG][NPIX];   // (cr,cg,cb,T)
__device__ int    g_done[NTILE];           // zero-init; winner resets each run

__device__ __forceinline__ float ex2_fast(float x) {
    float y; asm("ex2.approx.f32 %0, %1;" : "=f"(y) : "f"(x)); return y;
}
__device__ __forceinline__ float lg2_fast(float x) {
    float y; asm("lg2.approx.f32 %0, %1;" : "=f"(y) : "f"(x)); return y;
}
__device__ __forceinline__ u64 pack2(float lo, float hi) {
    u64 r; asm("mov.b64 %0, {%1, %2};" : "=l"(r) : "f"(lo), "f"(hi)); return r;
}
__device__ __forceinline__ void unpack2(u64 v, float& lo, float& hi) {
    asm("mov.b64 {%0, %1}, %2;" : "=f"(lo), "=f"(hi) : "l"(v));
}
__device__ __forceinline__ u64 f2add(u64 a, u64 b) {
    u64 d; asm("add.rn.f32x2 %0, %1, %2;" : "=l"(d) : "l"(a), "l"(b)); return d;
}
__device__ __forceinline__ u64 f2sub(u64 a, u64 b) {
    u64 d; asm("sub.rn.f32x2 %0, %1, %2;" : "=l"(d) : "l"(a), "l"(b)); return d;
}
__device__ __forceinline__ u64 f2mul(u64 a, u64 b) {
    u64 d; asm("mul.rn.f32x2 %0, %1, %2;" : "=l"(d) : "l"(a), "l"(b)); return d;
}
__device__ __forceinline__ u64 f2fma(u64 a, u64 b, u64 c) {
    u64 d; asm("fma.rn.f32x2 %0, %1, %2, %3;" : "=l"(d) : "l"(a), "l"(b), "l"(c)); return d;
}
__device__ __forceinline__ float4 ldcg4(const float4* p) {
    float4 v;
    asm volatile("ld.global.cg.v4.f32 {%0,%1,%2,%3}, [%4];"
                 : "=f"(v.x), "=f"(v.y), "=f"(v.z), "=f"(v.w) : "l"(p));
    return v;
}

// ---- fused: per-warp cull -> smem lists; 2-pixel f32x2 composite; fused combine ----
__global__ __launch_bounds__(128)
void gs_raster_kernel(const float* __restrict__ pxy,
                      const float* __restrict__ icov,
                      const float* __restrict__ radius,
                      const float* __restrict__ colors,
                      const float* __restrict__ opacity,
                      float* __restrict__ out)
{
    __shared__ u16        s_idx[SEG];    // survivor ids, depth order within each chunk
    __shared__ int        s_cnt[NWARP];
    __shared__ float4     s_A[STAGE];    // -mx, a2, b2, d
    __shared__ ulonglong2 s_B[STAGE];    // (-my,-my), (c2,c2)
    __shared__ ulonglong2 s_C[STAGE];    // (r,r), (g,g)
    __shared__ u64        s_D[STAGE];    // (b,b)
    __shared__ int        s_ret;

    const int tid  = threadIdx.x;        // 0..127
    const int lane = tid & 31;
    const int warp = tid >> 5;
    const int tile = blockIdx.x;
    const int seg  = blockIdx.y;
    const int tx   = tile & 15, ty = tile >> 4;

    // ---- cull phase: warp w culls chunk w of this block's segment ----
    {
        const float tx0 = (float)(tx * TILE), tx1 = tx0 + (float)TILE;
        const float ty0 = (float)(ty * TILE), ty1 = ty0 + (float)TILE;
        const int beg = seg * SEG + warp * CHUNKSZ;
        int cnt = 0;
        #pragma unroll 4
        for (int it = 0; it < CHUNKSZ / 32; ++it) {          // 8 iterations
            const int g = beg + it * 32 + lane;
            const float2 mp = ((const float2*)pxy)[g];
            const float  r  = radius[g];
            const bool keep = (floorf(mp.x - r) <= tx1) && (ceilf(mp.x + r) >= tx0)
                           && (floorf(mp.y - r) <= ty1) && (ceilf(mp.y + r) >= ty0);
            const unsigned m = __ballot_sync(0xffffffffu, keep);
            if (keep) {
                const int idx = cnt + __popc(m & ((1u << lane) - 1u));  // order-preserving
                s_idx[warp * CHUNKSZ + idx] = (u16)g;
            }
            cnt += __popc(m);
        }
        if (lane == 0) s_cnt[warp] = cnt;
    }
    __syncthreads();

    int total = 0;
    #pragma unroll
    for (int c = 0; c < NWARP; ++c) total += s_cnt[c];

    // two pixels per thread: (x, y0) and (x, y0+8), same x
    const int xo = tid >> 3;             // 0..15
    const int yo = tid & 7;              // 0..7
    const float fx  = (float)(tx * TILE + xo);
    const u64   fyp = pack2((float)(ty * TILE + yo), (float)(ty * TILE + yo + 8));

    u64 T   = pack2(1.0f, 1.0f);
    u64 crr = 0, cgg = 0, cbb = 0;
    float tmax = 1.0f;

    for (int base = 0; base < total; base += STAGE) {
        if (base > 0 && __syncthreads_count(tmax >= MIN_W) == 0) break;

        const int s = base + tid;
        if (s < total) {
            int rem = s, c = 0;          // locate per-warp sub-list
            #pragma unroll
            for (int k = 0; k < NWARP - 1; ++k)
                if (rem >= s_cnt[c]) { rem -= s_cnt[c]; ++c; }
            const int gi = (int)s_idx[c * CHUNKSZ + rem];

            const float2 mp = ((const float2*)pxy)[gi];
            const float4 ic = ((const float4*)icov)[gi];
            const float a2 = -0.5f * LOG2E * ic.x;
            const float b2 = -LOG2E * ic.y;
            const float c2 = -0.5f * LOG2E * ic.w;
            const float d  = -lg2_fast(1.0f + ex2_fast(-LOG2E * opacity[gi])); // log2(sigmoid)
            const float cr0 = colors[3*gi+0], cg0 = colors[3*gi+1], cb0 = colors[3*gi+2];

            s_A[tid] = make_float4(-mp.x, a2, b2, d);
            s_B[tid] = make_ulonglong2(pack2(-mp.y, -mp.y), pack2(c2, c2));
            s_C[tid] = make_ulonglong2(pack2(cr0, cr0), pack2(cg0, cg0));
            s_D[tid] = pack2(cb0, cb0);
        }
        const int m   = min(STAGE, total - base);
        const int pm4 = (m + 3) & ~3;
        if (tid >= m && tid < pm4) {     // alpha == 0 sentinels (q = -1e30)
            s_A[tid] = make_float4(0.0f, 0.0f, 0.0f, -1e30f);
            s_B[tid] = make_ulonglong2(0ull, 0ull);
            s_C[tid] = make_ulonglong2(0ull, 0ull);
            s_D[tid] = 0ull;
        }
        __syncthreads();

        if (tmax >= MIN_W) {
            for (int j = 0; j < pm4; j += 4) {   // 4 gaussians x 2 pixels = 8 indep evals
                u64 qp[4];
                #pragma unroll
                for (int p = 0; p < 4; ++p) {
                    const float4 A = s_A[j + p];
                    const ulonglong2 B = s_B[j + p];
                    const float dx = fx + A.x;
                    const float u  = A.y * dx;
                    const float qs = fmaf(u, dx, A.w);       // a2*dx^2 + d
                    const float v  = A.z * dx;               // b2*dx
                    const u64 dyp = f2add(fyp, B.x);
                    const u64 w1  = f2fma(B.y, dyp, pack2(v, v));   // c2*dy + b2*dx
                    qp[p] = f2fma(w1, dyp, pack2(qs, qs));
                }
                #pragma unroll
                for (int p = 0; p < 4; ++p) {
                    float q0, q1; unpack2(qp[p], q0, q1);
                    const u64 alp = pack2(ex2_fast(q0), ex2_fast(q1)); // alpha per pixel
                    const ulonglong2 C = s_C[j + p];
                    const u64 wp = f2mul(T, alp);            // T*alpha
                    T = f2sub(T, wp);                         // T *= (1-alpha)
                    crr = f2fma(wp, C.x, crr);
                    cgg = f2fma(wp, C.y, cgg);
                    cbb = f2fma(wp, s_D[j + p], cbb);
                }
                float t0, t1; unpack2(T, t0, t1);
                tmax = fmaxf(t0, t1);
                if (tmax < MIN_W) break;         // monotone
            }
        }
    }

    // write per-segment scratch for both pixels
    float t0, t1;  unpack2(T,   t0, t1);
    float r0, r1;  unpack2(crr, r0, r1);
    float g0, g1;  unpack2(cgg, g0, g1);
    float b0, b1;  unpack2(cbb, b0, b1);
    const int px   = tx * TILE + xo;
    const int py0  = ty * TILE + yo;
    const int pix0 = px * H_IMG + py0;
    const int pix1 = pix0 + 8;
    g_scratch[seg][pix0] = make_float4(r0, g0, b0, t0);
    g_scratch[seg][pix1] = make_float4(r1, g1, b1, t1);

    // ---- fused combine: last block per tile composites the 8 segments ----
    __threadfence();
    __syncthreads();
    if (tid == 0) s_ret = atomicAdd(&g_done[tile], 1);
    __syncthreads();
    if (s_ret == NSEG - 1) {
        #pragma unroll
        for (int h = 0; h < 2; ++h) {
            const int pix = (h == 0) ? pix0 : pix1;
            float rr = 0.0f, gg = 0.0f, bb = 0.0f;   // back-to-front
            #pragma unroll
            for (int k = NSEG - 1; k >= 0; --k) {
                const float4 v = ldcg4(&g_scratch[k][pix]);
                rr = fmaf(v.w, rr, v.x);
                gg = fmaf(v.w, gg, v.y);
                bb = fmaf(v.w, bb, v.z);
            }
            out[3*pix + 0] = rr;
            out[3*pix + 1] = gg;
            out[3*pix + 2] = bb;
        }
        if (tid == 0) g_done[tile] = 0;              // reset for next graph replay
    }
}

extern "C" void kernel_launch(void* const* d_in, const int* in_sizes, int n_in,
                              void* d_out, int out_size) {
    const float* pxy     = (const float*)d_in[0];
    const float* icov    = (const float*)d_in[1];
    const float* radius  = (const float*)d_in[2];
    const float* colors  = (const float*)d_in[3];
    const float* opacity = (const float*)d_in[4];
    float* out = (float*)d_out;

    dim3 rgrid(NTILE, NSEG);
    gs_raster_kernel<<<rgrid, 128>>>(pxy, icov, radius, colors, opacity, out);
}